// round 2
// baseline (speedup 1.0000x reference)
#include <cuda_runtime.h>
#include <cuda_bf16.h>
#include <cstdint>

// ---------------- problem constants ----------------
#define BB     4
#define QQ     300
#define NC     81
#define NROWS  1200          // B*Q
#define HOUT   160
#define POUT   25600         // 160*160
#define MT     400           // num targets
#define HIN    256

// ---------------- GEMM constants -------------------
#define GM 2432              // 2*1200 padded to 19*128
#define GN 448               // 400 padded to 7*64
#define GK 25600
#define BM 128
#define BN 64
#define BK 32
#define STAGES 3
#define LDK (BK + 8)         // padded smem row: 40 bf16 = 80B, conflict-free
#define NKT (GK / BK)        // 800

// ---------------- scratch (device globals; zero-initialized) ----------------
__device__ __nv_bfloat16 g_A[(size_t)GM * GK];   // rows [0,1200)=X bf16, [1200,2400)=sigmoid(X), rest stay 0
__device__ __nv_bfloat16 g_T[(size_t)GN * GK];   // resized targets bf16 (rows >=400 stay 0)
__device__ float g_S[(size_t)GM * GN];           // GEMM output: S1 rows 0..1199, S2 rows 1200..2399
__device__ float g_L[NROWS];                     // rowsum log_sigmoid(-x)
__device__ float g_P[NROWS];                     // rowsum sigmoid(x)
__device__ float g_TS[MT];                       // target mask sums
__device__ float g_prob[NROWS * NC];             // softmax probs

// ---------------- helpers ----------------
__device__ __forceinline__ float2 blockReduceSum2(float a, float b) {
    __shared__ float sa[32], sb[32];
    int lane = threadIdx.x & 31, wid = threadIdx.x >> 5;
    #pragma unroll
    for (int o = 16; o; o >>= 1) {
        a += __shfl_xor_sync(0xFFFFFFFFu, a, o);
        b += __shfl_xor_sync(0xFFFFFFFFu, b, o);
    }
    if (lane == 0) { sa[wid] = a; sb[wid] = b; }
    __syncthreads();
    int nw = blockDim.x >> 5;
    a = (threadIdx.x < (unsigned)nw) ? sa[threadIdx.x] : 0.f;
    b = (threadIdx.x < (unsigned)nw) ? sb[threadIdx.x] : 0.f;
    if (wid == 0) {
        #pragma unroll
        for (int o = 16; o; o >>= 1) {
            a += __shfl_xor_sync(0xFFFFFFFFu, a, o);
            b += __shfl_xor_sync(0xFFFFFFFFu, b, o);
        }
    }
    return make_float2(a, b);
}

__device__ __forceinline__ uint32_t smem_u32(const void* p) {
    return (uint32_t)__cvta_generic_to_shared(p);
}

// ---------------- kernel 1: prep pred masks ----------------
// per row: bf16(X) -> g_A[row], bf16(sigmoid) -> g_A[row+1200],
// rowsum(log_sigmoid(-x)) -> g_L, rowsum(sigmoid) -> g_P
__global__ void __launch_bounds__(256) prep_k(const float* __restrict__ pm) {
    const int row = blockIdx.x;
    const float4* src = (const float4*)(pm + (size_t)row * POUT);
    uint2* dx = (uint2*)(g_A + (size_t)row * GK);
    uint2* dp = (uint2*)(g_A + (size_t)(row + NROWS) * GK);
    float ls = 0.f, ps = 0.f;
    for (int i = threadIdx.x; i < POUT / 4; i += blockDim.x) {
        float4 v = src[i];
        float x[4] = {v.x, v.y, v.z, v.w};
        float sg[4];
        #pragma unroll
        for (int j = 0; j < 4; j++) {
            float e = expf(-fabsf(x[j]));        // e^{-|x|}
            float inv = 1.f / (1.f + e);
            sg[j] = (x[j] >= 0.f) ? inv : e * inv;   // sigmoid(x)
            ls -= fmaxf(x[j], 0.f) + log1pf(e);      // log_sigmoid(-x) = -softplus(x)
            ps += sg[j];
        }
        __nv_bfloat162 x01, x23, s01, s23;
        x01.x = __float2bfloat16_rn(x[0]);  x01.y = __float2bfloat16_rn(x[1]);
        x23.x = __float2bfloat16_rn(x[2]);  x23.y = __float2bfloat16_rn(x[3]);
        s01.x = __float2bfloat16_rn(sg[0]); s01.y = __float2bfloat16_rn(sg[1]);
        s23.x = __float2bfloat16_rn(sg[2]); s23.y = __float2bfloat16_rn(sg[3]);
        uint2 wx, ws;
        wx.x = *reinterpret_cast<unsigned*>(&x01); wx.y = *reinterpret_cast<unsigned*>(&x23);
        ws.x = *reinterpret_cast<unsigned*>(&s01); ws.y = *reinterpret_cast<unsigned*>(&s23);
        dx[i] = wx;
        dp[i] = ws;
    }
    float2 r = blockReduceSum2(ls, ps);
    if (threadIdx.x == 0) { g_L[row] = r.x; g_P[row] = r.y; }
}

// ---------------- kernel 2: antialiased bilinear resize 256->160 ----------------
// matches jax.image.resize(method="bilinear", antialias=True):
// triangle kernel scaled by inv_scale=1.6, per-dim weight normalization over in-range taps
__global__ void resize_k(const float* __restrict__ tm) {
    const int oy = blockIdx.x;   // 0..159
    const int t  = blockIdx.y;   // 0..399
    __shared__ float rows[4][HIN];

    const float kinv = 1.0f / 1.6f;
    float sy = (oy + 0.5f) * 1.6f - 0.5f;
    int jy0 = (int)ceilf(sy - 1.6f);
    float wy[4]; float wsy = 0.f;
    #pragma unroll
    for (int r = 0; r < 4; r++) {
        int j = jy0 + r;
        float w = fmaxf(1.f - fabsf(sy - (float)j) * kinv, 0.f);
        if (j < 0 || j > HIN - 1) w = 0.f;
        wy[r] = w; wsy += w;
    }
    float inv_wsy = 1.f / wsy;

    const float* src = tm + (size_t)t * (HIN * HIN);
    for (int i = threadIdx.x; i < 4 * HIN; i += blockDim.x) {
        int r = i >> 8, c = i & (HIN - 1);
        int j = jy0 + r; j = min(max(j, 0), HIN - 1);
        rows[r][c] = src[j * HIN + c];
    }
    __syncthreads();

    int ox = threadIdx.x;
    if (ox < HOUT) {
        float sx = (ox + 0.5f) * 1.6f - 0.5f;
        int jx0 = (int)ceilf(sx - 1.6f);
        float wx[4]; float wsx = 0.f;
        int jc[4];
        #pragma unroll
        for (int c = 0; c < 4; c++) {
            int j = jx0 + c;
            float w = fmaxf(1.f - fabsf(sx - (float)j) * kinv, 0.f);
            if (j < 0 || j > HIN - 1) w = 0.f;
            wx[c] = w; wsx += w;
            jc[c] = min(max(j, 0), HIN - 1);
        }
        float inv_wsx = 1.f / wsx;
        float acc = 0.f;
        #pragma unroll
        for (int r = 0; r < 4; r++) {
            float ra = 0.f;
            #pragma unroll
            for (int c = 0; c < 4; c++) ra += wx[c] * rows[r][jc[c]];
            acc += wy[r] * ra;
        }
        acc *= inv_wsy * inv_wsx;
        g_T[(size_t)t * GK + oy * HOUT + ox] = __float2bfloat16_rn(acc);
    }
}

// ---------------- kernel 3: target mask sums ----------------
__global__ void __launch_bounds__(256) tsum_k() {
    const int t = blockIdx.x;
    const __nv_bfloat16* p = g_T + (size_t)t * GK;
    float s = 0.f;
    for (int i = threadIdx.x; i < POUT; i += 256) s += __bfloat162float(p[i]);
    float2 r = blockReduceSum2(s, 0.f);
    if (threadIdx.x == 0) g_TS[t] = r.x;
}

// ---------------- kernel 4: class softmax ----------------
__global__ void __launch_bounds__(128) softmax_k(const float* __restrict__ logits) {
    const int n = blockIdx.x;
    const int t = threadIdx.x;
    __shared__ float sh[128];
    float v = (t < NC) ? logits[(size_t)n * NC + t] : -1e30f;
    sh[t] = v; __syncthreads();
    #pragma unroll
    for (int s = 64; s; s >>= 1) { if (t < s) sh[t] = fmaxf(sh[t], sh[t + s]); __syncthreads(); }
    float mx = sh[0]; __syncthreads();
    float e = (t < NC) ? expf(v - mx) : 0.f;
    sh[t] = e; __syncthreads();
    #pragma unroll
    for (int s = 64; s; s >>= 1) { if (t < s) sh[t] += sh[t + s]; __syncthreads(); }
    float inv = 1.f / sh[0];
    if (t < NC) g_prob[(size_t)n * NC + t] = e * inv;
}

// ---------------- kernel 5: bf16 HMMA GEMM  [GM x GK] @ [GN x GK]^T -> [GM x GN] fp32 ----------------
#define CP16(dst, src) asm volatile("cp.async.cg.shared.global [%0], [%1], 16;\n" :: "r"(dst), "l"(src) : "memory")
#define LDSM4(r, addr) asm volatile("ldmatrix.sync.aligned.m8n8.x4.shared.b16 {%0,%1,%2,%3}, [%4];\n" \
    : "=r"((r)[0]), "=r"((r)[1]), "=r"((r)[2]), "=r"((r)[3]) : "r"(addr))
#define MMA16816(d, a, b0, b1) asm volatile( \
    "mma.sync.aligned.m16n8k16.row.col.f32.bf16.bf16.f32 " \
    "{%0,%1,%2,%3},{%4,%5,%6,%7},{%8,%9},{%0,%1,%2,%3};\n" \
    : "+f"((d)[0]), "+f"((d)[1]), "+f"((d)[2]), "+f"((d)[3]) \
    : "r"((a)[0]), "r"((a)[1]), "r"((a)[2]), "r"((a)[3]), "r"(b0), "r"(b1))

__device__ __forceinline__ void load_tiles(int s, int kt, int tid,
                                           const __nv_bfloat16* Ag, const __nv_bfloat16* Bg,
                                           __nv_bfloat16 (*As)[BM][LDK], __nv_bfloat16 (*Bs)[BN][LDK]) {
    const __nv_bfloat16* ag = Ag + (size_t)kt * BK;
    #pragma unroll
    for (int i = 0; i < 2; i++) {               // A: 128 rows * 4 chunks = 512, 2 per thread
        int c = tid + i * 256;
        int r = c >> 2, o = (c & 3) * 8;
        CP16(smem_u32(&As[s][r][o]), ag + (size_t)r * GK + o);
    }
    const __nv_bfloat16* bg = Bg + (size_t)kt * BK;
    {                                           // B: 64 rows * 4 chunks = 256, 1 per thread
        int r = tid >> 2, o = (tid & 3) * 8;
        CP16(smem_u32(&Bs[s][r][o]), bg + (size_t)r * GK + o);
    }
}

__global__ void __launch_bounds__(256, 1) gemm_k() {
    __shared__ __nv_bfloat16 As[STAGES][BM][LDK];
    __shared__ __nv_bfloat16 Bs[STAGES][BN][LDK];
    const int tid = threadIdx.x;
    const int bm = blockIdx.y * BM;
    const int bn = blockIdx.x * BN;
    const __nv_bfloat16* Ag = g_A + (size_t)bm * GK;
    const __nv_bfloat16* Bg = g_T + (size_t)bn * GK;

    const int lane = tid & 31, warp = tid >> 5;
    const int wm = (warp & 3) * 32;
    const int wn = (warp >> 2) * 32;
    const int grp = lane >> 3, rr = lane & 7;
    const int aRow = (grp & 1) * 8 + rr, aK = (grp >> 1) * 8;
    const int bRow = (grp >> 1) * 8 + rr, bK = (grp & 1) * 8;

    float acc[2][4][4];
    #pragma unroll
    for (int i = 0; i < 2; i++)
        #pragma unroll
        for (int j = 0; j < 4; j++)
            #pragma unroll
            for (int k = 0; k < 4; k++) acc[i][j][k] = 0.f;

    // prologue: preload STAGES-1 stages
    #pragma unroll
    for (int s = 0; s < STAGES - 1; s++) {
        load_tiles(s, s, tid, Ag, Bg, As, Bs);
        asm volatile("cp.async.commit_group;\n" ::: "memory");
    }

    for (int kt = 0; kt < NKT; kt++) {
        asm volatile("cp.async.wait_group 1;\n" ::: "memory");  // keep STAGES-2 in flight
        __syncthreads();
        int nf = kt + STAGES - 1;
        if (nf < NKT) {
            load_tiles(nf % STAGES, nf, tid, Ag, Bg, As, Bs);
            asm volatile("cp.async.commit_group;\n" ::: "memory");
        }
        const int ps = kt % STAGES;
        #pragma unroll
        for (int kk = 0; kk < BK; kk += 16) {
            uint32_t a[2][4], b[2][4];
            #pragma unroll
            for (int mi = 0; mi < 2; mi++) {
                uint32_t ad = smem_u32(&As[ps][wm + mi * 16 + aRow][kk + aK]);
                LDSM4(a[mi], ad);
            }
            #pragma unroll
            for (int bi = 0; bi < 2; bi++) {
                uint32_t bd = smem_u32(&Bs[ps][wn + bi * 16 + bRow][kk + bK]);
                LDSM4(b[bi], bd);
            }
            #pragma unroll
            for (int mi = 0; mi < 2; mi++)
                #pragma unroll
                for (int ni = 0; ni < 4; ni++) {
                    const uint32_t* bb = &b[ni >> 1][(ni & 1) * 2];
                    MMA16816(acc[mi][ni], a[mi], bb[0], bb[1]);
                }
        }
        __syncthreads();
    }

    // epilogue
    const int g = lane >> 2, tg = lane & 3;
    #pragma unroll
    for (int mi = 0; mi < 2; mi++)
        #pragma unroll
        for (int ni = 0; ni < 4; ni++) {
            size_t row = (size_t)(bm + wm + mi * 16 + g);
            int col = bn + wn + ni * 8 + tg * 2;
            *(float2*)&g_S[row * GN + col] = make_float2(acc[mi][ni][0], acc[mi][ni][1]);
            *(float2*)&g_S[(row + 8) * GN + col] = make_float2(acc[mi][ni][2], acc[mi][ni][3]);
        }
}

// ---------------- kernel 6: combine all cost terms ----------------
__global__ void __launch_bounds__(128) combine_k(const float* __restrict__ pboxes,
                                                 const float* __restrict__ tboxes,
                                                 const int* __restrict__ tids,
                                                 float* __restrict__ out) {
    const int n = blockIdx.y;
    const int m = blockIdx.x * 128 + threadIdx.x;
    if (m >= MT) return;

    const float4 pb = reinterpret_cast<const float4*>(pboxes)[n];
    const float4 tb = reinterpret_cast<const float4*>(tboxes)[m];

    float cost_bbox = fabsf(pb.x - tb.x) + fabsf(pb.y - tb.y) + fabsf(pb.z - tb.z) + fabsf(pb.w - tb.w);

    float px0 = pb.x - 0.5f * pb.z, py0 = pb.y - 0.5f * pb.w;
    float px1 = pb.x + 0.5f * pb.z, py1 = pb.y + 0.5f * pb.w;
    float tx0 = tb.x - 0.5f * tb.z, ty0 = tb.y - 0.5f * tb.w;
    float tx1 = tb.x + 0.5f * tb.z, ty1 = tb.y + 0.5f * tb.w;
    float area1 = (px1 - px0) * (py1 - py0);
    float area2 = (tx1 - tx0) * (ty1 - ty0);
    float lx = fmaxf(px0, tx0), ly = fmaxf(py0, ty0);
    float rx = fminf(px1, tx1), ry = fminf(py1, ty1);
    float iw = fmaxf(rx - lx, 0.f), ih = fmaxf(ry - ly, 0.f);
    float inter = iw * ih;
    float uni = area1 + area2 - inter;
    float iou = inter / uni;
    float ex = fminf(px0, tx0), ey = fminf(py0, ty0);
    float fx2 = fmaxf(px1, tx1), fy2 = fmaxf(py1, ty1);
    float ew = fmaxf(fx2 - ex, 0.f), eh = fmaxf(fy2 - ey, 0.f);
    float areae = ew * eh;
    float giou = iou - (areae - uni) / areae;

    int id = tids[m];
    float cclass = -g_prob[(size_t)n * NC + id];

    float s1 = g_S[(size_t)n * GN + m];
    float s2 = g_S[(size_t)(n + NROWS) * GN + m];
    float cmask = -(s1 + g_L[n]) / (float)POUT;
    float cdice = 1.f - (2.f * s2 + 1e-5f) / (g_P[n] + g_TS[m] + 1e-5f);

    out[(size_t)n * MT + m] = 5.f * cost_bbox + 2.f * (-giou) + 2.f * cclass
                            + 5.f * cmask + 5.f * cdice;
}

// ---------------- launch ----------------
extern "C" void kernel_launch(void* const* d_in, const int* in_sizes, int n_in,
                              void* d_out, int out_size) {
    (void)in_sizes; (void)n_in; (void)out_size;
    const float* logits = (const float*)d_in[0];
    const float* pboxes = (const float*)d_in[1];
    const float* pmasks = (const float*)d_in[2];
    const float* tboxes = (const float*)d_in[3];
    const float* tmasks = (const float*)d_in[4];
    const int*   tids   = (const int*)d_in[5];
    float* out = (float*)d_out;

    prep_k<<<NROWS, 256>>>(pmasks);
    resize_k<<<dim3(HOUT, MT), 160>>>(tmasks);
    tsum_k<<<MT, 256>>>();
    softmax_k<<<NROWS, 128>>>(logits);
    gemm_k<<<dim3(GN / BN, GM / BM), 256>>>();
    combine_k<<<dim3((MT + 127) / 128, NROWS), 128>>>(pboxes, tboxes, tids, out);
}

// round 5
// speedup vs baseline: 1.0478x; 1.0478x over previous
#include <cuda_runtime.h>
#include <cuda_bf16.h>
#include <cstdint>

// ---------------- problem constants ----------------
#define NC     81
#define NROWS  1200          // B*Q
#define HOUT   160
#define POUT   25600         // 160*160
#define MT     400           // num targets
#define HIN    256

// ---------------- GEMM constants -------------------
#define GM 2432              // 2*1200 padded to 19*128
#define GN 512               // 400 padded to 2*256
#define GK 25600
#define BM 128
#define BN 256
#define BK 32
#define MTILES 19
#define NTILES 2
#define KSPLIT 3
#define STAGES 3
#define LDKROW 40            // padded smem row: 40 bf16 = 80B

#define SM_A_BYTES (BM * LDKROW * 2)              // 10240
#define SM_B_BYTES (BN * LDKROW * 2)              // 20480
#define SM_STAGE   (SM_A_BYTES + SM_B_BYTES)      // 30720
#define GEMM_SMEM  (STAGES * SM_STAGE)            // 92160

#define RESIZE_LD   257
#define RESIZE_SMEM (HOUT * RESIZE_LD * 4)        // 164480

// ---------------- scratch (device globals; zero-initialized) ----------------
__device__ __align__(16) __nv_bfloat16 g_A[(size_t)GM * GK];  // [X; sigmoid(X)], pad rows 0
__device__ __align__(16) __nv_bfloat16 g_T[(size_t)GN * GK];  // resized targets, pad rows 0
__device__ float g_Sp[(size_t)KSPLIT * GM * GN];              // K-split partials
__device__ float g_L[NROWS];                                  // rowsum log_sigmoid(-x)
__device__ float g_P[NROWS];                                  // rowsum sigmoid(x)
__device__ float g_TS[MT];                                    // target mask sums
__device__ float g_prob[NROWS * NC];                          // softmax probs

// ---------------- helpers ----------------
__device__ __forceinline__ float2 blockReduceSum2(float a, float b) {
    __shared__ float sa[32], sb[32];
    int lane = threadIdx.x & 31, wid = threadIdx.x >> 5;
    #pragma unroll
    for (int o = 16; o; o >>= 1) {
        a += __shfl_xor_sync(0xFFFFFFFFu, a, o);
        b += __shfl_xor_sync(0xFFFFFFFFu, b, o);
    }
    if (lane == 0) { sa[wid] = a; sb[wid] = b; }
    __syncthreads();
    int nw = blockDim.x >> 5;
    a = (threadIdx.x < (unsigned)nw) ? sa[threadIdx.x] : 0.f;
    b = (threadIdx.x < (unsigned)nw) ? sb[threadIdx.x] : 0.f;
    if (wid == 0) {
        #pragma unroll
        for (int o = 16; o; o >>= 1) {
            a += __shfl_xor_sync(0xFFFFFFFFu, a, o);
            b += __shfl_xor_sync(0xFFFFFFFFu, b, o);
        }
    }
    return make_float2(a, b);
}

__device__ __forceinline__ uint32_t smem_u32(const void* p) {
    return (uint32_t)__cvta_generic_to_shared(p);
}

#define CP16(dst, src) asm volatile("cp.async.cg.shared.global [%0], [%1], 16;\n" :: "r"(dst), "l"(src) : "memory")
#define LDSM4(r, addr) asm volatile("ldmatrix.sync.aligned.m8n8.x4.shared.b16 {%0,%1,%2,%3}, [%4];\n" \
    : "=r"((r)[0]), "=r"((r)[1]), "=r"((r)[2]), "=r"((r)[3]) : "r"(addr))
#define MMA16816(d, a, b0, b1) asm volatile( \
    "mma.sync.aligned.m16n8k16.row.col.f32.bf16.bf16.f32 " \
    "{%0,%1,%2,%3},{%4,%5,%6,%7},{%8,%9},{%0,%1,%2,%3};\n" \
    : "+f"((d)[0]), "+f"((d)[1]), "+f"((d)[2]), "+f"((d)[3]) \
    : "r"((a)[0]), "r"((a)[1]), "r"((a)[2]), "r"((a)[3]), "r"(b0), "r"(b1))

// ---------------- kernel 1: prep pred masks ----------------
__global__ void __launch_bounds__(256) prep_k(const float* __restrict__ pm) {
    const int row = blockIdx.x;
    const float4* src = (const float4*)(pm + (size_t)row * POUT);
    uint2* dx = (uint2*)(g_A + (size_t)row * GK);
    uint2* dp = (uint2*)(g_A + (size_t)(row + NROWS) * GK);
    float ls = 0.f, ps = 0.f;
    for (int i = threadIdx.x; i < POUT / 4; i += blockDim.x) {
        float4 v = src[i];
        float x[4] = {v.x, v.y, v.z, v.w};
        float sg[4];
        #pragma unroll
        for (int j = 0; j < 4; j++) {
            float e = __expf(-fabsf(x[j]));              // e^{-|x|}
            float inv = __fdividef(1.f, 1.f + e);
            sg[j] = (x[j] >= 0.f) ? inv : e * inv;       // sigmoid(x)
            ls -= fmaxf(x[j], 0.f) + __logf(1.f + e);    // log_sigmoid(-x) = -softplus(x)
            ps += sg[j];
        }
        __nv_bfloat162 x01, x23, s01, s23;
        x01.x = __float2bfloat16_rn(x[0]);  x01.y = __float2bfloat16_rn(x[1]);
        x23.x = __float2bfloat16_rn(x[2]);  x23.y = __float2bfloat16_rn(x[3]);
        s01.x = __float2bfloat16_rn(sg[0]); s01.y = __float2bfloat16_rn(sg[1]);
        s23.x = __float2bfloat16_rn(sg[2]); s23.y = __float2bfloat16_rn(sg[3]);
        uint2 wx, ws;
        wx.x = *reinterpret_cast<unsigned*>(&x01); wx.y = *reinterpret_cast<unsigned*>(&x23);
        ws.x = *reinterpret_cast<unsigned*>(&s01); ws.y = *reinterpret_cast<unsigned*>(&s23);
        dx[i] = wx;
        dp[i] = ws;
    }
    float2 r = blockReduceSum2(ls, ps);
    if (threadIdx.x == 0) { g_L[row] = r.x; g_P[row] = r.y; }
}

// ---------------- kernel 2: antialiased separable resize 256->160, one CTA per mask ---------
// matches jax.image.resize(method="bilinear", antialias=True):
// triangle kernel scaled by scale=1.6, per-dim weight normalization over in-range taps
__global__ void __launch_bounds__(256) resize2_k(const float* __restrict__ tm) {
    extern __shared__ float tmp[];   // [160][257] vertical-resized intermediate
    const int t = blockIdx.x;
    const int tid = threadIdx.x;
    const float* src = tm + (size_t)t * (HIN * HIN);
    const float kinv = 1.0f / 1.6f;

    // pass 1: vertical resize 256 rows -> 160 rows, all 256 columns
    {
        const int x = tid;   // 0..255
        for (int oy = 0; oy < HOUT; oy++) {
            float sy = (oy + 0.5f) * 1.6f - 0.5f;
            int jy0 = (int)ceilf(sy - 1.6f);
            float acc = 0.f, wsum = 0.f;
            #pragma unroll
            for (int r = 0; r < 4; r++) {
                int j = jy0 + r;
                float w = fmaxf(1.f - fabsf(sy - (float)j) * kinv, 0.f);
                if (j < 0 || j > HIN - 1) w = 0.f;
                int jj = min(max(j, 0), HIN - 1);
                acc += w * src[jj * HIN + x];
                wsum += w;
            }
            tmp[oy * RESIZE_LD + x] = acc * __fdividef(1.f, wsum);
        }
    }
    __syncthreads();

    // pass 2: horizontal resize 256 cols -> 160 cols
    for (int i = tid; i < POUT; i += 256) {
        int oy = i / HOUT, ox = i - oy * HOUT;
        float sx = (ox + 0.5f) * 1.6f - 0.5f;
        int jx0 = (int)ceilf(sx - 1.6f);
        float acc = 0.f, wsum = 0.f;
        #pragma unroll
        for (int c = 0; c < 4; c++) {
            int j = jx0 + c;
            float w = fmaxf(1.f - fabsf(sx - (float)j) * kinv, 0.f);
            if (j < 0 || j > HIN - 1) w = 0.f;
            int jj = min(max(j, 0), HIN - 1);
            acc += w * tmp[oy * RESIZE_LD + jj];
            wsum += w;
        }
        g_T[(size_t)t * GK + i] = __float2bfloat16_rn(acc * __fdividef(1.f, wsum));
    }
}

// ---------------- kernel 3: target mask sums ----------------
__global__ void __launch_bounds__(256) tsum_k() {
    const int t = blockIdx.x;
    const __nv_bfloat16* p = g_T + (size_t)t * GK;
    float s = 0.f;
    for (int i = threadIdx.x; i < POUT; i += 256) s += __bfloat162float(p[i]);
    float2 r = blockReduceSum2(s, 0.f);
    if (threadIdx.x == 0) g_TS[t] = r.x;
}

// ---------------- kernel 4: class softmax ----------------
__global__ void __launch_bounds__(128) softmax_k(const float* __restrict__ logits) {
    const int n = blockIdx.x;
    const int t = threadIdx.x;
    __shared__ float sh[128];
    float v = (t < NC) ? logits[(size_t)n * NC + t] : -1e30f;
    sh[t] = v; __syncthreads();
    #pragma unroll
    for (int s = 64; s; s >>= 1) { if (t < s) sh[t] = fmaxf(sh[t], sh[t + s]); __syncthreads(); }
    float mx = sh[0]; __syncthreads();
    float e = (t < NC) ? expf(v - mx) : 0.f;
    sh[t] = e; __syncthreads();
    #pragma unroll
    for (int s = 64; s; s >>= 1) { if (t < s) sh[t] += sh[t + s]; __syncthreads(); }
    float inv = 1.f / sh[0];
    if (t < NC) g_prob[(size_t)n * NC + t] = e * inv;
}

// ---------------- kernel 5: HMMA GEMM, 64x64 warp tiles, K-split ----------------
// grid (NTILES, MTILES, KSPLIT), 256 threads (8 warps = 2 m-rows x 4 n-cols of 64x64).
__global__ void __launch_bounds__(256, 1) gemm_k() {
    extern __shared__ __align__(16) char smem[];
    const uint32_t sb = smem_u32(smem);
    const int tid = threadIdx.x;
    const int ks = blockIdx.z;
    const int bm = blockIdx.y * BM;
    const int bn = blockIdx.x * BN;

    // K split of 800 chunks: 267/267/266
    const int nkt = (ks == 2) ? 266 : 267;
    const int ch0 = ks * 267;

    const __nv_bfloat16* Ag = g_A + (size_t)bm * GK;

    const int lane = tid & 31, warp = tid >> 5;
    const int wm = (warp >> 2) * 64;        // 0 or 64
    const int wn = (warp & 3) * 64;         // 0,64,128,192
    const int grp = lane >> 3, rr = lane & 7;
    const int aRow = (grp & 1) * 8 + rr, aK = (grp >> 1) * 8;
    const int bRow = (grp >> 1) * 8 + rr, bK = (grp & 1) * 8;

    float acc[4][8][4];
    #pragma unroll
    for (int i = 0; i < 4; i++)
        #pragma unroll
        for (int j = 0; j < 8; j++)
            #pragma unroll
            for (int k = 0; k < 4; k++) acc[i][j][k] = 0.f;

    auto load_stage = [&](int s, int kt) {
        const size_t kbase = (size_t)kt * BK;
        const uint32_t abase = sb + s * SM_STAGE;
        #pragma unroll
        for (int i = 0; i < 2; i++) {                       // A: 512 x 16B chunks
            int c = tid + i * 256;
            int r = c >> 2, seg = c & 3;
            CP16(abase + (uint32_t)(r * LDKROW + seg * 8) * 2, Ag + (size_t)r * GK + kbase + seg * 8);
        }
        const uint32_t bbase = abase + SM_A_BYTES;
        #pragma unroll
        for (int i = 0; i < 4; i++) {                       // B: 1024 x 16B chunks
            int c = tid + i * 256;
            int r = c >> 2, seg = c & 3;
            CP16(bbase + (uint32_t)(r * LDKROW + seg * 8) * 2,
                 g_T + (size_t)(bn + r) * GK + kbase + seg * 8);
        }
        asm volatile("cp.async.commit_group;\n" ::: "memory");
    };

    load_stage(0, ch0 + 0);
    load_stage(1, ch0 + 1);

    for (int kt = 0; kt < nkt; kt++) {
        const int s = kt % STAGES;
        if (kt + 2 < nkt) { asm volatile("cp.async.wait_group 1;\n" ::: "memory"); }
        else              { asm volatile("cp.async.wait_group 0;\n" ::: "memory"); }
        __syncthreads();
        if (kt + 2 < nkt) load_stage((kt + 2) % STAGES, ch0 + kt + 2);

        const uint32_t abase = sb + s * SM_STAGE;
        const uint32_t bbase = abase + SM_A_BYTES;
        #pragma unroll
        for (int kk = 0; kk < BK; kk += 16) {
            uint32_t a[4][4], b[4][4];
            #pragma unroll
            for (int mi = 0; mi < 4; mi++) {
                uint32_t ad = abase + (uint32_t)((wm + mi * 16 + aRow) * LDKROW + kk + aK) * 2;
                LDSM4(a[mi], ad);
            }
            #pragma unroll
            for (int bi = 0; bi < 4; bi++) {
                uint32_t bd = bbase + (uint32_t)((wn + bi * 16 + bRow) * LDKROW + kk + bK) * 2;
                LDSM4(b[bi], bd);
            }
            #pragma unroll
            for (int mi = 0; mi < 4; mi++)
                #pragma unroll
                for (int ni = 0; ni < 8; ni++) {
                    const uint32_t* bb = &b[ni >> 1][(ni & 1) * 2];
                    MMA16816(acc[mi][ni], a[mi], bb[0], bb[1]);
                }
        }
        __syncthreads();
    }

    // epilogue: write K-split partial tile
    const int g = lane >> 2, tg = lane & 3;
    float* Sp = g_Sp + (size_t)ks * GM * GN;
    #pragma unroll
    for (int mi = 0; mi < 4; mi++)
        #pragma unroll
        for (int ni = 0; ni < 8; ni++) {
            size_t row = (size_t)(bm + wm + mi * 16 + g);
            int col = bn + wn + ni * 8 + tg * 2;
            *(float2*)&Sp[row * GN + col] = make_float2(acc[mi][ni][0], acc[mi][ni][1]);
            *(float2*)&Sp[(row + 8) * GN + col] = make_float2(acc[mi][ni][2], acc[mi][ni][3]);
        }
}

// ---------------- kernel 6: combine (incl. K-split reduction) ----------------
__global__ void __launch_bounds__(128) combine_k(const float* __restrict__ pboxes,
                                                 const float* __restrict__ tboxes,
                                                 const int* __restrict__ tids,
                                                 float* __restrict__ out) {
    const int n = blockIdx.y;
    const int m = blockIdx.x * 128 + threadIdx.x;
    if (m >= MT) return;

    const float4 pb = reinterpret_cast<const float4*>(pboxes)[n];
    const float4 tb = reinterpret_cast<const float4*>(tboxes)[m];

    float cost_bbox = fabsf(pb.x - tb.x) + fabsf(pb.y - tb.y) + fabsf(pb.z - tb.z) + fabsf(pb.w - tb.w);

    float px0 = pb.x - 0.5f * pb.z, py0 = pb.y - 0.5f * pb.w;
    float px1 = pb.x + 0.5f * pb.z, py1 = pb.y + 0.5f * pb.w;
    float tx0 = tb.x - 0.5f * tb.z, ty0 = tb.y - 0.5f * tb.w;
    float tx1 = tb.x + 0.5f * tb.z, ty1 = tb.y + 0.5f * tb.w;
    float area1 = (px1 - px0) * (py1 - py0);
    float area2 = (tx1 - tx0) * (ty1 - ty0);
    float lx = fmaxf(px0, tx0), ly = fmaxf(py0, ty0);
    float rx = fminf(px1, tx1), ry = fminf(py1, ty1);
    float iw = fmaxf(rx - lx, 0.f), ih = fmaxf(ry - ly, 0.f);
    float inter = iw * ih;
    float uni = area1 + area2 - inter;
    float iou = inter / uni;
    float ex = fminf(px0, tx0), ey = fminf(py0, ty0);
    float fx2 = fmaxf(px1, tx1), fy2 = fmaxf(py1, ty1);
    float ew = fmaxf(fx2 - ex, 0.f), eh = fmaxf(fy2 - ey, 0.f);
    float areae = ew * eh;
    float giou = iou - (areae - uni) / areae;

    int id = tids[m];
    float cclass = -g_prob[(size_t)n * NC + id];

    float s1 = 0.f, s2 = 0.f;
    #pragma unroll
    for (int s = 0; s < KSPLIT; s++) {
        s1 += g_Sp[((size_t)s * GM + n) * GN + m];
        s2 += g_Sp[((size_t)s * GM + n + NROWS) * GN + m];
    }

    float cmask = -(s1 + g_L[n]) / (float)POUT;
    float cdice = 1.f - (2.f * s2 + 1e-5f) / (g_P[n] + g_TS[m] + 1e-5f);

    out[(size_t)n * MT + m] = 5.f * cost_bbox + 2.f * (-giou) + 2.f * cclass
                            + 5.f * cmask + 5.f * cdice;
}

// ---------------- launch ----------------
extern "C" void kernel_launch(void* const* d_in, const int* in_sizes, int n_in,
                              void* d_out, int out_size) {
    (void)in_sizes; (void)n_in; (void)out_size;
    const float* logits = (const float*)d_in[0];
    const float* pboxes = (const float*)d_in[1];
    const float* pmasks = (const float*)d_in[2];
    const float* tboxes = (const float*)d_in[3];
    const float* tmasks = (const float*)d_in[4];
    const int*   tids   = (const int*)d_in[5];
    float* out = (float*)d_out;

    cudaFuncSetAttribute(gemm_k, cudaFuncAttributeMaxDynamicSharedMemorySize, GEMM_SMEM);
    cudaFuncSetAttribute(resize2_k, cudaFuncAttributeMaxDynamicSharedMemorySize, RESIZE_SMEM);

    prep_k<<<NROWS, 256>>>(pmasks);
    resize2_k<<<MT, 256, RESIZE_SMEM>>>(tmasks);
    tsum_k<<<MT, 256>>>();
    softmax_k<<<NROWS, 128>>>(logits);
    gemm_k<<<dim3(NTILES, MTILES, KSPLIT), 256, GEMM_SMEM>>>();
    combine_k<<<dim3((MT + 127) / 128, NROWS), 128>>>(pboxes, tboxes, tids, out);
}